// round 13
// baseline (speedup 1.0000x reference)
#include <cuda_runtime.h>
#include <cuda_fp16.h>
#include <math.h>
#include <stdint.h>

// ---------------- problem constants (fixed shapes) ----------------
#define Tn    2048
#define Hn    2048
#define En    16
#define In    768
#define TWOI  1536
#define TOPK  4
#define RROWS (Tn*TOPK)
#define EPH   8               // experts per half

// ---------------- device scratch ----------------
__device__ int   g_counts[En];
__device__ int   g_cursor[En];
__device__ int   g_offsets[En + 1];
__device__ int   g_rowTok[RROWS];
__device__ int   g_tokRow[Tn * TOPK];
__device__ float g_tokW[Tn * TOPK];
__device__ float g_rowW[RROWS];
__device__ int   g_tokExp[Tn * TOPK];
__device__ __half g_mid [(size_t)RROWS * In];
__device__ __half g_Yrh [(size_t)RROWS * Hn];
__device__ __half g_mids[(size_t)Tn * In];
// fp16 operand copies
__device__ __half g_xh  [(size_t)Tn * Hn];
__device__ __half g_guph[(size_t)En * TWOI * Hn];
__device__ __half g_dwnh[(size_t)En * Hn * In];
__device__ __half g_sguh[(size_t)TWOI * Hn];
__device__ __half g_sdwh[(size_t)Hn * In];

__device__ __forceinline__ uint32_t smem_u32(const void* p) {
    uint32_t a;
    asm("{ .reg .u64 t; cvta.to.shared.u64 t, %1; cvt.u32.u64 %0, t; }" : "=r"(a) : "l"(p));
    return a;
}

__device__ __forceinline__ void cp_async16(uint32_t dst, const void* src) {
    asm volatile("cp.async.cg.shared.global [%0], [%1], 16;" :: "r"(dst), "l"(src) : "memory");
}
#define CP_COMMIT() asm volatile("cp.async.commit_group;" ::: "memory")
#define CP_WAIT(n)  asm volatile("cp.async.wait_group %0;" :: "n"(n) : "memory")

__device__ __forceinline__ void mma_f16(float& d0, float& d1, float& d2, float& d3,
                                        uint32_t a0, uint32_t a1, uint32_t a2, uint32_t a3,
                                        uint32_t b0, uint32_t b1) {
    asm volatile(
        "mma.sync.aligned.m16n8k16.row.col.f32.f16.f16.f32 "
        "{%0,%1,%2,%3}, {%4,%5,%6,%7}, {%8,%9}, {%0,%1,%2,%3};"
        : "+f"(d0), "+f"(d1), "+f"(d2), "+f"(d3)
        : "r"(a0), "r"(a1), "r"(a2), "r"(a3), "r"(b0), "r"(b1));
}

__device__ __forceinline__ uint2 cvt4(float4 f) {
    __half2 h0 = __floats2half2_rn(f.x, f.y);
    __half2 h1 = __floats2half2_rn(f.z, f.w);
    return make_uint2(*reinterpret_cast<uint32_t*>(&h0), *reinterpret_cast<uint32_t*>(&h1));
}

// ---------------- conversion passes ----------------
__global__ void h16conv_kernel(const float4* __restrict__ in, uint2* __restrict__ out, int n4) {
    int stride = gridDim.x * blockDim.x;
    for (int i = blockIdx.x * blockDim.x + threadIdx.x; i < n4; i += stride)
        out[i] = cvt4(in[i]);
}

// gup chunk: interleave gate/up rows within each expert block of 2I rows
__global__ void gupconv_kernel(const float4* __restrict__ in, uint2* __restrict__ out, int n4) {
    const int HV = Hn / 4;
    int stride = gridDim.x * blockDim.x;
    for (int i = blockIdx.x * blockDim.x + threadIdx.x; i < n4; i += stride) {
        int row = i / HV, c = i - row * HV;
        int e = row / TWOI, r = row - e * TWOI;
        int src = (r & 1) ? (In + (r >> 1)) : (r >> 1);
        out[i] = cvt4(in[((size_t)e * TWOI + src) * HV + c]);
    }
}

__global__ void sguconv_kernel(const float4* __restrict__ gin, const float4* __restrict__ uin,
                               uint2* __restrict__ out, int n4) {
    const int HV = Hn / 4;
    int stride = gridDim.x * blockDim.x;
    for (int i = blockIdx.x * blockDim.x + threadIdx.x; i < n4; i += stride) {
        int row = i / HV, c = i - row * HV;
        int j = row >> 1;
        const float4* src = (row & 1) ? uin : gin;
        out[i] = cvt4(src[(size_t)j * HV + c]);
    }
}

// ---------------- init / router / prefix / scatter ----------------
__global__ void init_kernel() {
    int i = threadIdx.x;
    if (i < En) { g_counts[i] = 0; g_cursor[i] = 0; }
}

__global__ void router_kernel(const float* __restrict__ x,
                              const float* __restrict__ rw,
                              const float* __restrict__ eb) {
    __shared__ float sx[Hn];
    __shared__ float ssc[En];
    int t = blockIdx.x;
    const float* xr = x + (size_t)t * Hn;
    for (int i = threadIdx.x; i < Hn; i += blockDim.x) sx[i] = xr[i];
    __syncthreads();

    int w = threadIdx.x >> 5, l = threadIdx.x & 31;
    if (w < En) {
        const float* wr = rw + (size_t)w * Hn;
        float s = 0.f;
        #pragma unroll 8
        for (int i = l; i < Hn; i += 32) s += sx[i] * wr[i];
        #pragma unroll
        for (int o = 16; o > 0; o >>= 1) s += __shfl_down_sync(0xffffffffu, s, o);
        if (l == 0) ssc[w] = s;
    }
    __syncthreads();

    if (threadIdx.x == 0) {
        float sig[En], sel[En];
        #pragma unroll
        for (int e = 0; e < En; e++) {
            sig[e] = 1.f / (1.f + expf(-ssc[e]));
            sel[e] = sig[e] + eb[e];
        }
        int idx[TOPK];
        #pragma unroll
        for (int k = 0; k < TOPK; k++) {
            int best = 0; float bv = -1e30f;
            #pragma unroll
            for (int e = 0; e < En; e++)
                if (sel[e] > bv) { bv = sel[e]; best = e; }
            idx[k] = best; sel[best] = -1e30f;
        }
        float wsum = 0.f;
        #pragma unroll
        for (int k = 0; k < TOPK; k++) wsum += sig[idx[k]];
        float inv = 1.f / (wsum + 1e-20f);
        #pragma unroll
        for (int k = 0; k < TOPK; k++) {
            g_tokExp[t * TOPK + k] = idx[k];
            g_tokW[t * TOPK + k]   = sig[idx[k]] * inv;
            atomicAdd(&g_counts[idx[k]], 1);
        }
    }
}

__global__ void prefix_kernel() {
    g_offsets[0] = 0;
    for (int e = 0; e < En; e++) g_offsets[e + 1] = g_offsets[e] + g_counts[e];
}

__global__ void scatter_kernel() {
    int t = blockIdx.x * blockDim.x + threadIdx.x;
    if (t >= Tn) return;
    #pragma unroll
    for (int k = 0; k < TOPK; k++) {
        int e = g_tokExp[t * TOPK + k];
        int pos = atomicAdd(&g_cursor[e], 1);
        int row = g_offsets[e] + pos;
        g_rowTok[row] = t;
        g_tokRow[t * TOPK + k] = row;
        g_rowW[row] = g_tokW[t * TOPK + k];
    }
}

// ---------------- fp16 mma.sync GEMM, cp.async 4-stage pipeline ----------------
#define BM_ 128
#define BN_ 256
#define BK_ 64
#define ABYTES (BM_ * BK_ * 2)
#define BBYTES (BN_ * BK_ * 2)
#define STAGEB (ABYTES + BBYTES)
#define NSTAGE 4
#define SMTOT  (NSTAGE * STAGEB)        // 196608

__global__ __launch_bounds__(256) void hmma_kernel(
    const __half* __restrict__ A, const __half* __restrict__ B, void* __restrict__ Cv,
    int useGather, int useCounts, int fixedM, int fuseSilu, int halfOut, int zbase,
    int K, int ldc, size_t bStrideZ)
{
    extern __shared__ char smem[];
    int z = blockIdx.z + zbase;
    int M, rowbase;
    if (useCounts) { M = g_counts[z]; rowbase = g_offsets[z]; }
    else           { M = fixedM;      rowbase = 0; }
    int m0 = blockIdx.y * BM_;
    if (m0 >= M) return;
    int n0 = blockIdx.x * BN_;
    const __half* Bz = B + (size_t)z * bStrideZ;

    const int tid = threadIdx.x;
    const int wid = tid >> 5, lane = tid & 31;
    const int q = lane >> 2, e = lane & 3;
    const int wm = wid & 1, wn = wid >> 1;
    const uint32_t sbase = smem_u32(smem);

    const __half* aptr[4];
    uint32_t adst[4];
    #pragma unroll
    for (int i = 0; i < 4; i++) {
        int slot = tid + i * 256;
        int row = slot >> 3, g = slot & 7;
        int gr = m0 + row;
        int cl = gr < M ? gr : (M - 1);
        int src = useGather ? g_rowTok[rowbase + cl] : (rowbase + cl);
        aptr[i] = A + (size_t)src * K + g * 8;
        adst[i] = sbase + (uint32_t)(row * 128 + ((g ^ (row & 7)) << 4));
    }
    const __half* bptr[8];
    uint32_t bdst[8];
    #pragma unroll
    for (int i = 0; i < 8; i++) {
        int slot = tid + i * 256;
        int row = slot >> 3, g = slot & 7;
        bptr[i] = Bz + (size_t)(n0 + row) * K + g * 8;
        bdst[i] = sbase + (uint32_t)(ABYTES + row * 128 + ((g ^ (row & 7)) << 4));
    }

    float acc[4][8][4];
    #pragma unroll
    for (int i = 0; i < 4; i++)
        #pragma unroll
        for (int j = 0; j < 8; j++)
            #pragma unroll
            for (int v = 0; v < 4; v++) acc[i][j][v] = 0.f;

    const int nk = K / BK_;

    #pragma unroll
    for (int s = 0; s < NSTAGE - 1; s++) {
        uint32_t so = (uint32_t)(s * STAGEB);
        int k0 = s * BK_;
        #pragma unroll
        for (int i = 0; i < 4; i++) cp_async16(adst[i] + so, aptr[i] + k0);
        #pragma unroll
        for (int i = 0; i < 8; i++) cp_async16(bdst[i] + so, bptr[i] + k0);
        CP_COMMIT();
    }

    for (int kt = 0; kt < nk; kt++) {
        CP_WAIT(NSTAGE - 2);
        __syncthreads();

        int ns = kt + NSTAGE - 1;
        if (ns < nk) {
            uint32_t so = (uint32_t)((ns & (NSTAGE - 1)) * STAGEB);
            int k0 = ns * BK_;
            #pragma unroll
            for (int i = 0; i < 4; i++) cp_async16(adst[i] + so, aptr[i] + k0);
            #pragma unroll
            for (int i = 0; i < 8; i++) cp_async16(bdst[i] + so, bptr[i] + k0);
        }
        CP_COMMIT();

        const char* As = smem + (kt & (NSTAGE - 1)) * STAGEB;
        const char* Bs = As + ABYTES;
        const char* aBase = As + ((wm * 64 + q) * 128 + e * 4);
        const char* bBase = Bs + ((wn * 64 + q) * 128 + e * 4);

        #pragma unroll
        for (int ks = 0; ks < 4; ks++) {
            int g0 = ((2 * ks)     ^ q) << 4;
            int g1 = ((2 * ks + 1) ^ q) << 4;
            uint32_t af[4][4];
            #pragma unroll
            for (int i = 0; i < 4; i++) {
                const char* p = aBase + i * 16 * 128;
                af[i][0] = *reinterpret_cast<const uint32_t*>(p + g0);
                af[i][1] = *reinterpret_cast<const uint32_t*>(p + g0 + 8 * 128);
                af[i][2] = *reinterpret_cast<const uint32_t*>(p + g1);
                af[i][3] = *reinterpret_cast<const uint32_t*>(p + g1 + 8 * 128);
            }
            #pragma unroll
            for (int jn = 0; jn < 8; jn++) {
                const char* p = bBase + jn * 8 * 128;
                uint32_t b0 = *reinterpret_cast<const uint32_t*>(p + g0);
                uint32_t b1 = *reinterpret_cast<const uint32_t*>(p + g1);
                #pragma unroll
                for (int i = 0; i < 4; i++)
                    mma_f16(acc[i][jn][0], acc[i][jn][1], acc[i][jn][2], acc[i][jn][3],
                            af[i][0], af[i][1], af[i][2], af[i][3], b0, b1);
            }
        }
    }

    // ---- epilogue ----
    if (fuseSilu) {
        __half* Ch = (__half*)Cv;
        #pragma unroll
        for (int i = 0; i < 4; i++) {
            int r0 = m0 + wm * 64 + i * 16 + q;
            int r1 = r0 + 8;
            float w0 = 1.f, w1 = 1.f;
            if (useCounts) {
                if (r0 < M) w0 = g_rowW[rowbase + r0];
                if (r1 < M) w1 = g_rowW[rowbase + r1];
            }
            #pragma unroll
            for (int jn = 0; jn < 8; jn++) {
                int j = (n0 + wn * 64 + jn * 8 + 2 * e) >> 1;
                if (r0 < M) {
                    float g = acc[i][jn][0], u = acc[i][jn][1];
                    float s = g / (1.f + expf(-g));
                    Ch[(size_t)(rowbase + r0) * ldc + j] = __float2half_rn(w0 * s * u);
                }
                if (r1 < M) {
                    float g = acc[i][jn][2], u = acc[i][jn][3];
                    float s = g / (1.f + expf(-g));
                    Ch[(size_t)(rowbase + r1) * ldc + j] = __float2half_rn(w1 * s * u);
                }
            }
        }
    } else if (halfOut) {
        __half* Ch = (__half*)Cv;
        #pragma unroll
        for (int i = 0; i < 4; i++) {
            int r0 = m0 + wm * 64 + i * 16 + q;
            int r1 = r0 + 8;
            #pragma unroll
            for (int jn = 0; jn < 8; jn++) {
                int cc = n0 + wn * 64 + jn * 8 + 2 * e;
                if (r0 < M) {
                    __half2 v = __floats2half2_rn(acc[i][jn][0], acc[i][jn][1]);
                    *reinterpret_cast<__half2*>(Ch + (size_t)(rowbase + r0) * ldc + cc) = v;
                }
                if (r1 < M) {
                    __half2 v = __floats2half2_rn(acc[i][jn][2], acc[i][jn][3]);
                    *reinterpret_cast<__half2*>(Ch + (size_t)(rowbase + r1) * ldc + cc) = v;
                }
            }
        }
    } else {
        float* C = (float*)Cv;
        #pragma unroll
        for (int i = 0; i < 4; i++) {
            int r0 = m0 + wm * 64 + i * 16 + q;
            int r1 = r0 + 8;
            #pragma unroll
            for (int jn = 0; jn < 8; jn++) {
                int cc = n0 + wn * 64 + jn * 8 + 2 * e;
                if (r0 < M) {
                    float2 v = make_float2(acc[i][jn][0], acc[i][jn][1]);
                    *reinterpret_cast<float2*>(C + (size_t)(rowbase + r0) * ldc + cc) = v;
                }
                if (r1 < M) {
                    float2 v = make_float2(acc[i][jn][2], acc[i][jn][3]);
                    *reinterpret_cast<float2*>(C + (size_t)(rowbase + r1) * ldc + cc) = v;
                }
            }
        }
    }
}

// ---------------- combine: out[t] += sum_k Yrh[row_k] (weights pre-applied) ----------------
__global__ void combine_kernel(float* __restrict__ out) {
    int t = blockIdx.x;
    int r0 = g_tokRow[t * 4 + 0], r1 = g_tokRow[t * 4 + 1];
    int r2 = g_tokRow[t * 4 + 2], r3 = g_tokRow[t * 4 + 3];
    const __half* y0 = g_Yrh + (size_t)r0 * Hn;
    const __half* y1 = g_Yrh + (size_t)r1 * Hn;
    const __half* y2 = g_Yrh + (size_t)r2 * Hn;
    const __half* y3 = g_Yrh + (size_t)r3 * Hn;
    float* o = out + (size_t)t * Hn;
    for (int c = threadIdx.x * 2; c < Hn; c += blockDim.x * 2) {
        float2 v = *reinterpret_cast<float2*>(o + c);
        float2 a0 = __half22float2(*reinterpret_cast<const __half2*>(y0 + c));
        float2 a1 = __half22float2(*reinterpret_cast<const __half2*>(y1 + c));
        float2 a2 = __half22float2(*reinterpret_cast<const __half2*>(y2 + c));
        float2 a3 = __half22float2(*reinterpret_cast<const __half2*>(y3 + c));
        v.x += a0.x + a1.x + a2.x + a3.x;
        v.y += a0.y + a1.y + a2.y + a3.y;
        *reinterpret_cast<float2*>(o + c) = v;
    }
}

// -------- launch: half-split gup conv + gate_up, dedicated streams --------
extern "C" void kernel_launch(void* const* d_in, const int* in_sizes, int n_in,
                              void* d_out, int out_size) {
    const float* x    = (const float*)d_in[0];
    const float* rw   = (const float*)d_in[1];
    const float* eb   = (const float*)d_in[2];
    const float* gup  = (const float*)d_in[3];
    const float* dwn  = (const float*)d_in[4];
    const float* sgw  = (const float*)d_in[5];
    const float* suw  = (const float*)d_in[6];
    const float* sdw  = (const float*)d_in[7];
    float* out = (float*)d_out;

    static int inited = 0;
    static cudaStream_t s1, s2, s3;
    static cudaEvent_t evRoot, evScatter, evXh, evG0, evG1, evDwn, evShared, evM1;
    if (!inited) {
        cudaFuncSetAttribute(hmma_kernel, cudaFuncAttributeMaxDynamicSharedMemorySize, SMTOT);
        cudaStreamCreateWithFlags(&s1, cudaStreamNonBlocking);
        cudaStreamCreateWithFlags(&s2, cudaStreamNonBlocking);
        cudaStreamCreateWithFlags(&s3, cudaStreamNonBlocking);
        cudaEventCreateWithFlags(&evRoot,    cudaEventDisableTiming);
        cudaEventCreateWithFlags(&evScatter, cudaEventDisableTiming);
        cudaEventCreateWithFlags(&evXh,      cudaEventDisableTiming);
        cudaEventCreateWithFlags(&evG0,      cudaEventDisableTiming);
        cudaEventCreateWithFlags(&evG1,      cudaEventDisableTiming);
        cudaEventCreateWithFlags(&evDwn,     cudaEventDisableTiming);
        cudaEventCreateWithFlags(&evShared,  cudaEventDisableTiming);
        cudaEventCreateWithFlags(&evM1,     cudaEventDisableTiming);
        inited = 1;
    }

    void *p_mid, *p_Yrh, *p_mids;
    void *p_xh, *p_guph, *p_dwnh, *p_sguh, *p_sdwh;
    cudaGetSymbolAddress(&p_mid,  g_mid);
    cudaGetSymbolAddress(&p_Yrh,  g_Yrh);
    cudaGetSymbolAddress(&p_mids, g_mids);
    cudaGetSymbolAddress(&p_xh,   g_xh);
    cudaGetSymbolAddress(&p_guph, g_guph);
    cudaGetSymbolAddress(&p_dwnh, g_dwnh);
    cudaGetSymbolAddress(&p_sguh, g_sguh);
    cudaGetSymbolAddress(&p_sdwh, g_sdwh);

    const int CVB = 512, CVG = 1024;
    const size_t GUPE = (size_t)TWOI * Hn;   // elems per expert

    // ---- fork ----
    cudaEventRecord(evRoot, 0);
    cudaStreamWaitEvent(s1, evRoot, 0);
    cudaStreamWaitEvent(s2, evRoot, 0);
    cudaStreamWaitEvent(s3, evRoot, 0);

    // main: routing chain
    init_kernel<<<1, 32>>>();
    router_kernel<<<Tn, 512>>>(x, rw, eb);
    prefix_kernel<<<1, 1>>>();
    scatter_kernel<<<(Tn + 255) / 256, 256>>>();
    cudaEventRecord(evScatter, 0);

    // s1: gupconv half0, half1, then dwnh conv
    gupconv_kernel<<<CVG, CVB, 0, s1>>>(
        (const float4*)gup, (uint2*)p_guph, (int)(EPH * GUPE / 4));
    cudaEventRecord(evG0, s1);
    gupconv_kernel<<<CVG, CVB, 0, s1>>>(
        (const float4*)(gup + EPH * GUPE),
        (uint2*)((__half*)p_guph + EPH * GUPE), (int)(EPH * GUPE / 4));
    cudaEventRecord(evG1, s1);
    h16conv_kernel<<<CVG, CVB, 0, s1>>>((const float4*)dwn, (uint2*)p_dwnh, En * Hn * In / 4);
    cudaEventRecord(evDwn, s1);

    // s2: xh conv first, then shared chain
    h16conv_kernel<<<CVG, CVB, 0, s2>>>((const float4*)x, (uint2*)p_xh, Tn * Hn / 4);
    cudaEventRecord(evXh, s2);
    sguconv_kernel<<<CVG, CVB, 0, s2>>>((const float4*)sgw, (const float4*)suw,
                                        (uint2*)p_sguh, TWOI * Hn / 4);
    h16conv_kernel<<<CVG, CVB, 0, s2>>>((const float4*)sdw, (uint2*)p_sdwh, Hn * In / 4);
    hmma_kernel<<<dim3(TWOI / BN_, Tn / BM_, 1), 256, SMTOT, s2>>>(
        (const __half*)p_xh, (const __half*)p_sguh, p_mids,
        0, 0, Tn, /*fuseSilu=*/1, 0, 0, Hn, /*ldc=*/In, 0);
    hmma_kernel<<<dim3(Hn / BN_, Tn / BM_, 1), 256, SMTOT, s2>>>(
        (const __half*)p_mids, (const __half*)p_sdwh, out,
        0, 0, Tn, 0, 0, 0, In, Hn, 0);
    cudaEventRecord(evShared, s2);

    // main: gate_up half-0 (scatter by stream order; waits xh + gup-h0 conv)
    cudaStreamWaitEvent(0, evXh, 0);
    cudaStreamWaitEvent(0, evG0, 0);
    hmma_kernel<<<dim3(TWOI / BN_, Tn / BM_, EPH), 256, SMTOT>>>(
        (const __half*)p_xh, (const __half*)p_guph, p_mid,
        1, 1, 0, /*fuseSilu=*/1, 0, /*zbase=*/0, Hn, /*ldc=*/In, (size_t)TWOI * Hn);

    // s3: gate_up half-1 (dedicated stream; co-packs with half-0 tail)
    cudaStreamWaitEvent(s3, evScatter, 0);
    cudaStreamWaitEvent(s3, evXh, 0);
    cudaStreamWaitEvent(s3, evG1, 0);
    hmma_kernel<<<dim3(TWOI / BN_, Tn / BM_, EPH), 256, SMTOT, s3>>>(
        (const __half*)p_xh, (const __half*)p_guph, p_mid,
        1, 1, 0, /*fuseSilu=*/1, 0, /*zbase=*/EPH, Hn, /*ldc=*/In, (size_t)TWOI * Hn);
    cudaEventRecord(evM1, s3);

    // main: routed down (needs both mid halves + dwnh conv) -> fp16 Yrh
    cudaStreamWaitEvent(0, evM1, 0);
    cudaStreamWaitEvent(0, evDwn, 0);
    hmma_kernel<<<dim3(Hn / BN_, Tn / BM_, En), 256, SMTOT>>>(
        (const __half*)p_mid, (const __half*)p_dwnh, p_Yrh,
        0, 1, 0, 0, /*halfOut=*/1, /*zbase=*/0, In, Hn, (size_t)Hn * In);

    // join
    cudaStreamWaitEvent(0, evShared, 0);
    combine_kernel<<<Tn, 256>>>(out);
}

// round 14
// speedup vs baseline: 1.0551x; 1.0551x over previous
#include <cuda_runtime.h>
#include <cuda_fp16.h>
#include <math.h>
#include <stdint.h>

// ---------------- problem constants (fixed shapes) ----------------
#define Tn    2048
#define Hn    2048
#define En    16
#define In    768
#define TWOI  1536
#define TOPK  4
#define RROWS (Tn*TOPK)

// ---------------- device scratch ----------------
__device__ int   g_counts[En];
__device__ int   g_cursor[En];
__device__ int   g_offsets[En + 1];
__device__ int   g_rowTok[RROWS];
__device__ int   g_tokRow[Tn * TOPK];
__device__ float g_tokW[Tn * TOPK];
__device__ float g_rowW[RROWS];
__device__ int   g_tokExp[Tn * TOPK];
__device__ __half g_mid [(size_t)RROWS * In];
__device__ __half g_Yrh [(size_t)RROWS * Hn];
__device__ __half g_mids[(size_t)Tn * In];
// fp16 operand copies
__device__ __half g_xh  [(size_t)Tn * Hn];
__device__ __half g_guph[(size_t)En * TWOI * Hn];
__device__ __half g_dwnh[(size_t)En * Hn * In];
__device__ __half g_sguh[(size_t)TWOI * Hn];
__device__ __half g_sdwh[(size_t)Hn * In];

__device__ __forceinline__ uint32_t smem_u32(const void* p) {
    uint32_t a;
    asm("{ .reg .u64 t; cvta.to.shared.u64 t, %1; cvt.u32.u64 %0, t; }" : "=r"(a) : "l"(p));
    return a;
}

__device__ __forceinline__ void cp_async16(uint32_t dst, const void* src) {
    asm volatile("cp.async.cg.shared.global [%0], [%1], 16;" :: "r"(dst), "l"(src) : "memory");
}
#define CP_COMMIT() asm volatile("cp.async.commit_group;" ::: "memory")
#define CP_WAIT(n)  asm volatile("cp.async.wait_group %0;" :: "n"(n) : "memory")

__device__ __forceinline__ void mma_f16(float& d0, float& d1, float& d2, float& d3,
                                        uint32_t a0, uint32_t a1, uint32_t a2, uint32_t a3,
                                        uint32_t b0, uint32_t b1) {
    asm volatile(
        "mma.sync.aligned.m16n8k16.row.col.f32.f16.f16.f32 "
        "{%0,%1,%2,%3}, {%4,%5,%6,%7}, {%8,%9}, {%0,%1,%2,%3};"
        : "+f"(d0), "+f"(d1), "+f"(d2), "+f"(d3)
        : "r"(a0), "r"(a1), "r"(a2), "r"(a3), "r"(b0), "r"(b1));
}

__device__ __forceinline__ uint2 cvt4(float4 f) {
    __half2 h0 = __floats2half2_rn(f.x, f.y);
    __half2 h1 = __floats2half2_rn(f.z, f.w);
    return make_uint2(*reinterpret_cast<uint32_t*>(&h0), *reinterpret_cast<uint32_t*>(&h1));
}

// ---------------- conversion passes ----------------
__global__ void h16conv_kernel(const float4* __restrict__ in, uint2* __restrict__ out, int n4) {
    int stride = gridDim.x * blockDim.x;
    for (int i = blockIdx.x * blockDim.x + threadIdx.x; i < n4; i += stride)
        out[i] = cvt4(in[i]);
}

// gup [E, 2I, H]: out row 2j = gate row j, out row 2j+1 = up row j (per expert)
__global__ void gupconv_kernel(const float4* __restrict__ in, uint2* __restrict__ out, int n4) {
    const int HV = Hn / 4;
    int stride = gridDim.x * blockDim.x;
    for (int i = blockIdx.x * blockDim.x + threadIdx.x; i < n4; i += stride) {
        int row = i / HV, c = i - row * HV;
        int e = row / TWOI, r = row - e * TWOI;
        int src = (r & 1) ? (In + (r >> 1)) : (r >> 1);
        out[i] = cvt4(in[((size_t)e * TWOI + src) * HV + c]);
    }
}

__global__ void sguconv_kernel(const float4* __restrict__ gin, const float4* __restrict__ uin,
                               uint2* __restrict__ out, int n4) {
    const int HV = Hn / 4;
    int stride = gridDim.x * blockDim.x;
    for (int i = blockIdx.x * blockDim.x + threadIdx.x; i < n4; i += stride) {
        int row = i / HV, c = i - row * HV;
        int j = row >> 1;
        const float4* src = (row & 1) ? uin : gin;
        out[i] = cvt4(src[(size_t)j * HV + c]);
    }
}

// ---------------- init / router / prefix / scatter ----------------
__global__ void init_kernel() {
    int i = threadIdx.x;
    if (i < En) { g_counts[i] = 0; g_cursor[i] = 0; }
}

__global__ void router_kernel(const float* __restrict__ x,
                              const float* __restrict__ rw,
                              const float* __restrict__ eb) {
    __shared__ float sx[Hn];
    __shared__ float ssc[En];
    int t = blockIdx.x;
    const float* xr = x + (size_t)t * Hn;
    for (int i = threadIdx.x; i < Hn; i += blockDim.x) sx[i] = xr[i];
    __syncthreads();

    int w = threadIdx.x >> 5, l = threadIdx.x & 31;
    if (w < En) {
        const float* wr = rw + (size_t)w * Hn;
        float s = 0.f;
        #pragma unroll 8
        for (int i = l; i < Hn; i += 32) s += sx[i] * wr[i];
        #pragma unroll
        for (int o = 16; o > 0; o >>= 1) s += __shfl_down_sync(0xffffffffu, s, o);
        if (l == 0) ssc[w] = s;
    }
    __syncthreads();

    if (threadIdx.x == 0) {
        float sig[En], sel[En];
        #pragma unroll
        for (int e = 0; e < En; e++) {
            sig[e] = 1.f / (1.f + expf(-ssc[e]));
            sel[e] = sig[e] + eb[e];
        }
        int idx[TOPK];
        #pragma unroll
        for (int k = 0; k < TOPK; k++) {
            int best = 0; float bv = -1e30f;
            #pragma unroll
            for (int e = 0; e < En; e++)
                if (sel[e] > bv) { bv = sel[e]; best = e; }
            idx[k] = best; sel[best] = -1e30f;
        }
        float wsum = 0.f;
        #pragma unroll
        for (int k = 0; k < TOPK; k++) wsum += sig[idx[k]];
        float inv = 1.f / (wsum + 1e-20f);
        #pragma unroll
        for (int k = 0; k < TOPK; k++) {
            g_tokExp[t * TOPK + k] = idx[k];
            g_tokW[t * TOPK + k]   = sig[idx[k]] * inv;
            atomicAdd(&g_counts[idx[k]], 1);
        }
    }
}

__global__ void prefix_kernel() {
    g_offsets[0] = 0;
    for (int e = 0; e < En; e++) g_offsets[e + 1] = g_offsets[e] + g_counts[e];
}

__global__ void scatter_kernel() {
    int t = blockIdx.x * blockDim.x + threadIdx.x;
    if (t >= Tn) return;
    #pragma unroll
    for (int k = 0; k < TOPK; k++) {
        int e = g_tokExp[t * TOPK + k];
        int pos = atomicAdd(&g_cursor[e], 1);
        int row = g_offsets[e] + pos;
        g_rowTok[row] = t;
        g_tokRow[t * TOPK + k] = row;
        g_rowW[row] = g_tokW[t * TOPK + k];
    }
}

// ---------------- fp16 mma.sync GEMM, cp.async 4-stage pipeline ----------------
#define BM_ 128
#define BN_ 256
#define BK_ 64
#define ABYTES (BM_ * BK_ * 2)
#define BBYTES (BN_ * BK_ * 2)
#define STAGEB (ABYTES + BBYTES)
#define NSTAGE 4
#define SMTOT  (NSTAGE * STAGEB)        // 196608

__global__ __launch_bounds__(256) void hmma_kernel(
    const __half* __restrict__ A, const __half* __restrict__ B, void* __restrict__ Cv,
    int useGather, int useCounts, int fixedM, int fuseSilu, int halfOut,
    int K, int ldc, size_t bStrideZ)
{
    extern __shared__ char smem[];
    int z = blockIdx.z;
    int M, rowbase;
    if (useCounts) { M = g_counts[z]; rowbase = g_offsets[z]; }
    else           { M = fixedM;      rowbase = 0; }
    int m0 = blockIdx.y * BM_;
    if (m0 >= M) return;
    int n0 = blockIdx.x * BN_;
    const __half* Bz = B + (size_t)z * bStrideZ;

    const int tid = threadIdx.x;
    const int wid = tid >> 5, lane = tid & 31;
    const int q = lane >> 2, e = lane & 3;
    const int wm = wid & 1, wn = wid >> 1;
    const uint32_t sbase = smem_u32(smem);

    const __half* aptr[4];
    uint32_t adst[4];
    #pragma unroll
    for (int i = 0; i < 4; i++) {
        int slot = tid + i * 256;
        int row = slot >> 3, g = slot & 7;
        int gr = m0 + row;
        int cl = gr < M ? gr : (M - 1);
        int src = useGather ? g_rowTok[rowbase + cl] : (rowbase + cl);
        aptr[i] = A + (size_t)src * K + g * 8;
        adst[i] = sbase + (uint32_t)(row * 128 + ((g ^ (row & 7)) << 4));
    }
    const __half* bptr[8];
    uint32_t bdst[8];
    #pragma unroll
    for (int i = 0; i < 8; i++) {
        int slot = tid + i * 256;
        int row = slot >> 3, g = slot & 7;
        bptr[i] = Bz + (size_t)(n0 + row) * K + g * 8;
        bdst[i] = sbase + (uint32_t)(ABYTES + row * 128 + ((g ^ (row & 7)) << 4));
    }

    float acc[4][8][4];
    #pragma unroll
    for (int i = 0; i < 4; i++)
        #pragma unroll
        for (int j = 0; j < 8; j++)
            #pragma unroll
            for (int v = 0; v < 4; v++) acc[i][j][v] = 0.f;

    const int nk = K / BK_;

    #pragma unroll
    for (int s = 0; s < NSTAGE - 1; s++) {
        uint32_t so = (uint32_t)(s * STAGEB);
        int k0 = s * BK_;
        #pragma unroll
        for (int i = 0; i < 4; i++) cp_async16(adst[i] + so, aptr[i] + k0);
        #pragma unroll
        for (int i = 0; i < 8; i++) cp_async16(bdst[i] + so, bptr[i] + k0);
        CP_COMMIT();
    }

    for (int kt = 0; kt < nk; kt++) {
        CP_WAIT(NSTAGE - 2);
        __syncthreads();

        int ns = kt + NSTAGE - 1;
        if (ns < nk) {
            uint32_t so = (uint32_t)((ns & (NSTAGE - 1)) * STAGEB);
            int k0 = ns * BK_;
            #pragma unroll
            for (int i = 0; i < 4; i++) cp_async16(adst[i] + so, aptr[i] + k0);
            #pragma unroll
            for (int i = 0; i < 8; i++) cp_async16(bdst[i] + so, bptr[i] + k0);
        }
        CP_COMMIT();

        const char* As = smem + (kt & (NSTAGE - 1)) * STAGEB;
        const char* Bs = As + ABYTES;
        const char* aBase = As + ((wm * 64 + q) * 128 + e * 4);
        const char* bBase = Bs + ((wn * 64 + q) * 128 + e * 4);

        #pragma unroll
        for (int ks = 0; ks < 4; ks++) {
            int g0 = ((2 * ks)     ^ q) << 4;
            int g1 = ((2 * ks + 1) ^ q) << 4;
            uint32_t af[4][4];
            #pragma unroll
            for (int i = 0; i < 4; i++) {
                const char* p = aBase + i * 16 * 128;
                af[i][0] = *reinterpret_cast<const uint32_t*>(p + g0);
                af[i][1] = *reinterpret_cast<const uint32_t*>(p + g0 + 8 * 128);
                af[i][2] = *reinterpret_cast<const uint32_t*>(p + g1);
                af[i][3] = *reinterpret_cast<const uint32_t*>(p + g1 + 8 * 128);
            }
            #pragma unroll
            for (int jn = 0; jn < 8; jn++) {
                const char* p = bBase + jn * 8 * 128;
                uint32_t b0 = *reinterpret_cast<const uint32_t*>(p + g0);
                uint32_t b1 = *reinterpret_cast<const uint32_t*>(p + g1);
                #pragma unroll
                for (int i = 0; i < 4; i++)
                    mma_f16(acc[i][jn][0], acc[i][jn][1], acc[i][jn][2], acc[i][jn][3],
                            af[i][0], af[i][1], af[i][2], af[i][3], b0, b1);
            }
        }
    }

    // ---- epilogue ----
    if (fuseSilu) {
        __half* Ch = (__half*)Cv;
        #pragma unroll
        for (int i = 0; i < 4; i++) {
            int r0 = m0 + wm * 64 + i * 16 + q;
            int r1 = r0 + 8;
            float w0 = 1.f, w1 = 1.f;
            if (useCounts) {
                if (r0 < M) w0 = g_rowW[rowbase + r0];
                if (r1 < M) w1 = g_rowW[rowbase + r1];
            }
            #pragma unroll
            for (int jn = 0; jn < 8; jn++) {
                int j = (n0 + wn * 64 + jn * 8 + 2 * e) >> 1;
                if (r0 < M) {
                    float g = acc[i][jn][0], u = acc[i][jn][1];
                    float s = g / (1.f + expf(-g));
                    Ch[(size_t)(rowbase + r0) * ldc + j] = __float2half_rn(w0 * s * u);
                }
                if (r1 < M) {
                    float g = acc[i][jn][2], u = acc[i][jn][3];
                    float s = g / (1.f + expf(-g));
                    Ch[(size_t)(rowbase + r1) * ldc + j] = __float2half_rn(w1 * s * u);
                }
            }
        }
    } else if (halfOut) {
        __half* Ch = (__half*)Cv;
        #pragma unroll
        for (int i = 0; i < 4; i++) {
            int r0 = m0 + wm * 64 + i * 16 + q;
            int r1 = r0 + 8;
            #pragma unroll
            for (int jn = 0; jn < 8; jn++) {
                int cc = n0 + wn * 64 + jn * 8 + 2 * e;
                if (r0 < M) {
                    __half2 v = __floats2half2_rn(acc[i][jn][0], acc[i][jn][1]);
                    *reinterpret_cast<__half2*>(Ch + (size_t)(rowbase + r0) * ldc + cc) = v;
                }
                if (r1 < M) {
                    __half2 v = __floats2half2_rn(acc[i][jn][2], acc[i][jn][3]);
                    *reinterpret_cast<__half2*>(Ch + (size_t)(rowbase + r1) * ldc + cc) = v;
                }
            }
        }
    } else {
        float* C = (float*)Cv;
        #pragma unroll
        for (int i = 0; i < 4; i++) {
            int r0 = m0 + wm * 64 + i * 16 + q;
            int r1 = r0 + 8;
            #pragma unroll
            for (int jn = 0; jn < 8; jn++) {
                int cc = n0 + wn * 64 + jn * 8 + 2 * e;
                if (r0 < M) {
                    float2 v = make_float2(acc[i][jn][0], acc[i][jn][1]);
                    *reinterpret_cast<float2*>(C + (size_t)(rowbase + r0) * ldc + cc) = v;
                }
                if (r1 < M) {
                    float2 v = make_float2(acc[i][jn][2], acc[i][jn][3]);
                    *reinterpret_cast<float2*>(C + (size_t)(rowbase + r1) * ldc + cc) = v;
                }
            }
        }
    }
}

// ---------------- combine: out[t] += sum_k Yrh[row_k] (weights pre-applied) ----------------
__global__ void combine_kernel(float* __restrict__ out) {
    int t = blockIdx.x;
    int r0 = g_tokRow[t * 4 + 0], r1 = g_tokRow[t * 4 + 1];
    int r2 = g_tokRow[t * 4 + 2], r3 = g_tokRow[t * 4 + 3];
    const __half* y0 = g_Yrh + (size_t)r0 * Hn;
    const __half* y1 = g_Yrh + (size_t)r1 * Hn;
    const __half* y2 = g_Yrh + (size_t)r2 * Hn;
    const __half* y3 = g_Yrh + (size_t)r3 * Hn;
    float* o = out + (size_t)t * Hn;
    for (int c = threadIdx.x * 2; c < Hn; c += blockDim.x * 2) {
        float2 v = *reinterpret_cast<float2*>(o + c);
        float2 a0 = __half22float2(*reinterpret_cast<const __half2*>(y0 + c));
        float2 a1 = __half22float2(*reinterpret_cast<const __half2*>(y1 + c));
        float2 a2 = __half22float2(*reinterpret_cast<const __half2*>(y2 + c));
        float2 a3 = __half22float2(*reinterpret_cast<const __half2*>(y3 + c));
        v.x += a0.x + a1.x + a2.x + a3.x;
        v.y += a0.y + a1.y + a2.y + a3.y;
        *reinterpret_cast<float2*>(o + c) = v;
    }
}

// -------- launch (R12 fork-join; s1 high-priority so gupconv wins DRAM) --------
extern "C" void kernel_launch(void* const* d_in, const int* in_sizes, int n_in,
                              void* d_out, int out_size) {
    const float* x    = (const float*)d_in[0];
    const float* rw   = (const float*)d_in[1];
    const float* eb   = (const float*)d_in[2];
    const float* gup  = (const float*)d_in[3];
    const float* dwn  = (const float*)d_in[4];
    const float* sgw  = (const float*)d_in[5];
    const float* suw  = (const float*)d_in[6];
    const float* sdw  = (const float*)d_in[7];
    float* out = (float*)d_out;

    static int inited = 0;
    static cudaStream_t s1, s2;
    static cudaEvent_t evRoot, evXh, evGup, evDwn, evShared;
    if (!inited) {
        cudaFuncSetAttribute(hmma_kernel, cudaFuncAttributeMaxDynamicSharedMemorySize, SMTOT);
        int prLow = 0, prHigh = 0;
        cudaDeviceGetStreamPriorityRange(&prLow, &prHigh);
        cudaStreamCreateWithPriority(&s1, cudaStreamNonBlocking, prHigh);  // critical convs
        cudaStreamCreateWithPriority(&s2, cudaStreamNonBlocking, prLow);   // shared chain
        cudaEventCreateWithFlags(&evRoot,   cudaEventDisableTiming);
        cudaEventCreateWithFlags(&evXh,     cudaEventDisableTiming);
        cudaEventCreateWithFlags(&evGup,    cudaEventDisableTiming);
        cudaEventCreateWithFlags(&evDwn,    cudaEventDisableTiming);
        cudaEventCreateWithFlags(&evShared, cudaEventDisableTiming);
        inited = 1;
    }

    void *p_mid, *p_Yrh, *p_mids;
    void *p_xh, *p_guph, *p_dwnh, *p_sguh, *p_sdwh;
    cudaGetSymbolAddress(&p_mid,  g_mid);
    cudaGetSymbolAddress(&p_Yrh,  g_Yrh);
    cudaGetSymbolAddress(&p_mids, g_mids);
    cudaGetSymbolAddress(&p_xh,   g_xh);
    cudaGetSymbolAddress(&p_guph, g_guph);
    cudaGetSymbolAddress(&p_dwnh, g_dwnh);
    cudaGetSymbolAddress(&p_sguh, g_sguh);
    cudaGetSymbolAddress(&p_sdwh, g_sdwh);

    const int CVB = 512, CVG = 1024;

    // ---- fork ----
    cudaEventRecord(evRoot, 0);
    cudaStreamWaitEvent(s1, evRoot, 0);
    cudaStreamWaitEvent(s2, evRoot, 0);

    // main: routing chain (parallel with conversions)
    init_kernel<<<1, 32>>>();
    router_kernel<<<Tn, 512>>>(x, rw, eb);
    prefix_kernel<<<1, 1>>>();
    scatter_kernel<<<(Tn + 255) / 256, 256>>>();

    // s1 (high prio): gupconv FIRST (gates routed critical path), then dwnh conv
    gupconv_kernel<<<CVG, CVB, 0, s1>>>((const float4*)gup, (uint2*)p_guph, En * TWOI * Hn / 4);
    cudaEventRecord(evGup, s1);
    h16conv_kernel<<<CVG, CVB, 0, s1>>>((const float4*)dwn, (uint2*)p_dwnh, En * Hn * In / 4);
    cudaEventRecord(evDwn, s1);

    // s2 (low prio): xh conv first, then shared chain
    h16conv_kernel<<<CVG, CVB, 0, s2>>>((const float4*)x, (uint2*)p_xh, Tn * Hn / 4);
    cudaEventRecord(evXh, s2);
    sguconv_kernel<<<CVG, CVB, 0, s2>>>((const float4*)sgw, (const float4*)suw,
                                        (uint2*)p_sguh, TWOI * Hn / 4);
    h16conv_kernel<<<CVG, CVB, 0, s2>>>((const float4*)sdw, (uint2*)p_sdwh, Hn * In / 4);
    hmma_kernel<<<dim3(TWOI / BN_, Tn / BM_, 1), 256, SMTOT, s2>>>(
        (const __half*)p_xh, (const __half*)p_sguh, p_mids,
        0, 0, Tn, /*fuseSilu=*/1, 0, Hn, /*ldc=*/In, 0);
    hmma_kernel<<<dim3(Hn / BN_, Tn / BM_, 1), 256, SMTOT, s2>>>(
        (const __half*)p_mids, (const __half*)p_sdwh, out,
        0, 0, Tn, 0, 0, In, Hn, 0);
    cudaEventRecord(evShared, s2);

    // main: routed gate_up (scatter by stream order; waits xh + gup convs)
    cudaStreamWaitEvent(0, evXh, 0);
    cudaStreamWaitEvent(0, evGup, 0);
    hmma_kernel<<<dim3(TWOI / BN_, Tn / BM_, En), 256, SMTOT>>>(
        (const __half*)p_xh, (const __half*)p_guph, p_mid,
        1, 1, 0, /*fuseSilu=*/1, 0, Hn, /*ldc=*/In, (size_t)TWOI * Hn);

    // main: routed down -> fp16 Yrh (rows pre-scaled by gate_up epilogue)
    cudaStreamWaitEvent(0, evDwn, 0);
    hmma_kernel<<<dim3(Hn / BN_, Tn / BM_, En), 256, SMTOT>>>(
        (const __half*)p_mid, (const __half*)p_dwnh, p_Yrh,
        0, 1, 0, 0, /*halfOut=*/1, In, Hn, (size_t)Hn * In);

    // join: combine needs out (s2) + Yrh (main)
    cudaStreamWaitEvent(0, evShared, 0);
    combine_kernel<<<Tn, 256>>>(out);
}